// round 2
// baseline (speedup 1.0000x reference)
#include <cuda_runtime.h>
#include <cstdint>

#define NB 4
#define NN 20000
#define MM 64
#define WL 8
#define NPAIRS (MM*NN*WL)      /* 10,240,000 pairs per X tensor */
#define NPB 32                 /* n's per chunk */
#define NCHUNK (NN/NPB)        /* 625 */
#define GX 74                  /* 74 x 2 batch-pairs = 148 blocks = 1/SM */

#define SMEM_TAB_BYTES   (NN*8)            /* 160000 */
#define SMEM_F_BYTES     (MM*33*8)         /* 16896, padded stride 33 */
#define SMEM_TOTAL       (SMEM_TAB_BYTES + 2*SMEM_F_BYTES + 512 + 64)  /* 194368 */

// ---------------- device scratch (static, no runtime allocation) -------------
__device__ unsigned g_cx1[NPAIRS];   // packed (i0 | i1<<16)
__device__ unsigned g_cx2[NPAIRS];
__device__ float2   g_tabA[2*NN];    // a transposed: [bp][n] = {a[2bp][n], a[2bp+1][n]}
__device__ float2   g_tabB[2*NN];
__device__ float    g_piT[MM*MM];    // piT[k*64+j] = pi[j][k]
__device__ float    g_pi1[MM];       // row sums of pi
__device__ float    g_pi2[MM];       // col sums of pi
__device__ int      g_is64;

// ---------------- dtype detection: int64 high words are all zero -------------
__global__ void k_detect(const unsigned* __restrict__ x) {
    __shared__ int s_nz;
    if (threadIdx.x == 0) s_nz = 0;
    __syncthreads();
    int nz = 0;
    for (int t = threadIdx.x; t < 2048; t += blockDim.x)
        nz |= (x[2*t + 1] != 0u);
    if (nz) atomicOr(&s_nz, 1);
    __syncthreads();
    if (threadIdx.x == 0) g_is64 = s_nz ? 0 : 1;
}

// ---------------- softmax over the whole 64x64 W ----------------------------
__global__ void k_pi(const float* __restrict__ Wm) {
    __shared__ float sp[MM*MM];
    __shared__ float rbuf[256];
    int tid = threadIdx.x;
    float lm = -1e30f;
    for (int i = tid; i < MM*MM; i += 256) { float v = Wm[i]; sp[i] = v; lm = fmaxf(lm, v); }
    rbuf[tid] = lm; __syncthreads();
    for (int s = 128; s > 0; s >>= 1) { if (tid < s) rbuf[tid] = fmaxf(rbuf[tid], rbuf[tid+s]); __syncthreads(); }
    float m = rbuf[0];
    __syncthreads();
    float ls = 0.f;
    for (int i = tid; i < MM*MM; i += 256) { float e = expf(sp[i] - m); sp[i] = e; ls += e; }
    rbuf[tid] = ls; __syncthreads();
    for (int s = 128; s > 0; s >>= 1) { if (tid < s) rbuf[tid] += rbuf[tid+s]; __syncthreads(); }
    float inv = 1.f / rbuf[0];
    __syncthreads();
    for (int i = tid; i < MM*MM; i += 256) sp[i] *= inv;
    __syncthreads();
    for (int i = tid; i < MM*MM; i += 256) {
        int j = i >> 6, k = i & 63;
        g_piT[k*MM + j] = sp[i];
    }
    if (tid < MM) {
        float s = 0.f;
        for (int k = 0; k < MM; k++) s += sp[tid*MM + k];
        g_pi1[tid] = s;
    } else if (tid < 2*MM) {
        int k = tid - MM;
        float s = 0.f;
        for (int j = 0; j < MM; j++) s += sp[j*MM + k];
        g_pi2[k] = s;
    }
}

// ---------------- build transposed float2 a-table from a0 -------------------
__global__ void k_tab(const float* __restrict__ a0) {
    int i = blockIdx.x * blockDim.x + threadIdx.x;
    if (i < NN) {
        g_tabA[i]      = make_float2(a0[i],        a0[NN + i]);
        g_tabA[NN + i] = make_float2(a0[2*NN + i], a0[3*NN + i]);
    }
}

// ---------------- pack index pairs into u32 (streaming) ---------------------
__global__ void k_compact(const void* __restrict__ x1, const void* __restrict__ x2) {
    int is64 = g_is64;
    int stride = gridDim.x * blockDim.x;
    int t0 = blockIdx.x * blockDim.x + threadIdx.x;
    if (is64) {
        const int4* p1 = (const int4*)x1;
        const int4* p2 = (const int4*)x2;
        for (int p = t0; p < NPAIRS; p += stride) {
            int4 v = __ldcs(p1 + p);
            int4 w = __ldcs(p2 + p);
            g_cx1[p] = (unsigned)v.x | ((unsigned)v.z << 16);
            g_cx2[p] = (unsigned)w.x | ((unsigned)w.z << 16);
        }
    } else {
        const int2* p1 = (const int2*)x1;
        const int2* p2 = (const int2*)x2;
        for (int p = t0; p < NPAIRS; p += stride) {
            int2 v = __ldcs(p1 + p);
            int2 w = __ldcs(p2 + p);
            g_cx1[p] = (unsigned)v.x | ((unsigned)v.y << 16);
            g_cx2[p] = (unsigned)w.x | ((unsigned)w.y << 16);
        }
    }
}

// ---------------- main iteration kernel --------------------------------------
__device__ __forceinline__ void gath_acc(unsigned v, const float2* tab, float2& f) {
    float2 A  = tab[v & 0xFFFFu];
    float2 Bv = tab[v >> 16];
    f.x = fmaxf(f.x, A.x * Bv.x);
    f.y = fmaxf(f.y, A.y * Bv.y);
}

__global__ void __launch_bounds__(256, 1) k_main(int srcSel, int write_out,
                                                 float* __restrict__ out) {
    extern __shared__ char smem[];
    float2* tab  = (float2*)smem;                                   // 20000 entries
    float2* F1s  = (float2*)(smem + SMEM_TAB_BYTES);                // [64][33]
    float2* F2s  = (float2*)(smem + SMEM_TAB_BYTES + SMEM_F_BYTES); // [64][33]
    float*  pi1s = (float*)(smem + SMEM_TAB_BYTES + 2*SMEM_F_BYTES);
    float*  pi2s = pi1s + MM;
    float2* red  = (float2*)(pi2s + MM);                            // [4][2]

    const int bp  = blockIdx.y;
    const float2* src = srcSel ? g_tabB : g_tabA;
    float2*       dst = srcSel ? g_tabA : g_tabB;
    const int tid = threadIdx.x;

    for (int i = tid; i < NN; i += 256) tab[i] = src[bp*NN + i];
    if (tid < MM) { pi1s[tid] = g_pi1[tid]; pi2s[tid] = g_pi2[tid]; }
    __syncthreads();

    const int warp = tid >> 5, lane = tid & 31;
    const int grp = tid >> 6, jj = tid & 63, half = (tid >> 5) & 1;

    for (int chunk = blockIdx.x; chunk < NCHUNK; chunk += gridDim.x) {
        const int n0 = chunk * NPB;

        // -------- phase 1: F1[j][n], F2[j][n] via smem gathers ----------
        #pragma unroll 2
        for (int p = 0; p < 8; p++) {
            int j = p*8 + warp;
            int n = n0 + lane;
            size_t pb = ((size_t)j * NN + n) * WL;
            const uint4* c1 = (const uint4*)(g_cx1 + pb);
            const uint4* c2 = (const uint4*)(g_cx2 + pb);
            uint4 q0 = __ldcs(c1);
            uint4 q1 = __ldcs(c1 + 1);
            uint4 r0 = __ldcs(c2);
            uint4 r1 = __ldcs(c2 + 1);
            float2 f1 = make_float2(0.f, 0.f);  // products are >= 0
            float2 f2 = make_float2(0.f, 0.f);
            gath_acc(q0.x, tab, f1); gath_acc(q0.y, tab, f1);
            gath_acc(q0.z, tab, f1); gath_acc(q0.w, tab, f1);
            gath_acc(q1.x, tab, f1); gath_acc(q1.y, tab, f1);
            gath_acc(q1.z, tab, f1); gath_acc(q1.w, tab, f1);
            gath_acc(r0.x, tab, f2); gath_acc(r0.y, tab, f2);
            gath_acc(r0.z, tab, f2); gath_acc(r0.w, tab, f2);
            gath_acc(r1.x, tab, f2); gath_acc(r1.y, tab, f2);
            gath_acc(r1.z, tab, f2); gath_acc(r1.w, tab, f2);
            F1s[j*33 + lane] = f1;
            F2s[j*33 + lane] = f2;
        }
        __syncthreads();

        // -------- phase 2: derived[n] = Eu + Ev - F1 . (pi @ F2) --------
        for (int r = 0; r < 8; r++) {
            int nl = r*4 + grp;
            float2 f1 = F1s[jj*33 + nl];
            float2 f2 = F2s[jj*33 + nl];
            float2 mv = make_float2(0.f, 0.f);
            #pragma unroll 16
            for (int k = 0; k < MM; k++) {
                float pw = __ldg(&g_piT[k*MM + jj]);
                float2 fk = F2s[k*33 + nl];   // broadcast within warp
                mv.x = fmaf(pw, fk.x, mv.x);
                mv.y = fmaf(pw, fk.y, mv.y);
            }
            float2 c;
            c.x = pi1s[jj]*f1.x + pi2s[jj]*f2.x - f1.x*mv.x;
            c.y = pi1s[jj]*f1.y + pi2s[jj]*f2.y - f1.y*mv.y;
            #pragma unroll
            for (int off = 16; off > 0; off >>= 1) {
                c.x += __shfl_down_sync(0xFFFFFFFFu, c.x, off);
                c.y += __shfl_down_sync(0xFFFFFFFFu, c.y, off);
            }
            if (lane == 0) red[grp*2 + half] = c;
            __syncthreads();
            if (jj == 0) {
                float2 d0 = red[grp*2], d1 = red[grp*2 + 1];
                float dx = d0.x + d1.x, dy = d0.y + d1.y;
                int n = n0 + nl;
                float2 ao = tab[n];
                float2 an;
                an.x = 1.f - (1.f - ao.x) * (1.f - dx);
                an.y = 1.f - (1.f - ao.y) * (1.f - dy);
                dst[bp*NN + n] = an;
                if (write_out) {
                    out[(2*bp)*NN + n]     = an.x;
                    out[(2*bp + 1)*NN + n] = an.y;
                }
            }
            __syncthreads();
        }
    }
}

// ---------------- launcher ----------------------------------------------------
extern "C" void kernel_launch(void* const* d_in, const int* in_sizes, int n_in,
                              void* d_out, int out_size) {
    const float* a0 = (const float*)d_in[0];
    const float* Wm = (const float*)d_in[1];
    const void*  x1 = d_in[2];
    const void*  x2 = d_in[3];
    float* out = (float*)d_out;

    cudaFuncSetAttribute(k_main, cudaFuncAttributeMaxDynamicSharedMemorySize, SMEM_TOTAL);

    k_detect<<<1, 256>>>((const unsigned*)x1);
    k_pi<<<1, 256>>>(Wm);
    k_tab<<<(NN + 255)/256, 256>>>(a0);
    k_compact<<<2048, 256>>>(x1, x2);

    dim3 g(GX, 2);
    k_main<<<g, 256, SMEM_TOTAL>>>(0, 0, out);   // iter 1: tabA -> tabB
    k_main<<<g, 256, SMEM_TOTAL>>>(1, 1, out);   // iter 2: tabB -> tabA + d_out
}

// round 3
// speedup vs baseline: 1.3410x; 1.3410x over previous
#include <cuda_runtime.h>
#include <cstdint>

#define NN 20000
#define MM 64
#define WL 8
#define NPAIRS (MM*NN*WL)      /* 10,240,000 pairs per X tensor */
#define NPB 32                 /* n's per chunk */
#define NCHUNK (NN/NPB)        /* 625 */
#define GX 74                  /* 74 x 2 batch-pairs = 148 blocks = 1/SM */
#define NT 512                 /* threads per block (16 warps) */

// ---- shared memory layout (bytes) ----
#define SZ_TAB   (NN*8)          /* 160000: a-table, float2 per n           */
#define SZ_F1    (MM*33*8)       /* 16896 : F1[j][n], pad 33                */
#define SZ_F2T   (NPB*66*8)      /* 16896 : F2T[n][k], pad 66 (even->f4 ok) */
#define SZ_PIT   (MM*MM*4)       /* 16384 : piT[k][j]                       */
#define SZ_P12   (2*MM*4)        /* 512   : pi1, pi2                        */
#define SZ_RED   (NPB*2*8)       /* 512   : cross-warp partials             */
#define OFF_F1   SZ_TAB
#define OFF_F2T  (OFF_F1+SZ_F1)
#define OFF_PIT  (OFF_F2T+SZ_F2T)
#define OFF_P12  (OFF_PIT+SZ_PIT)
#define OFF_RED  (OFF_P12+SZ_P12)
#define SMEM_TOTAL (OFF_RED+SZ_RED)   /* 211200 */

// ---------------- device scratch (static) ------------------------------------
__device__ unsigned g_cx1[NPAIRS];   // packed (i0 | i1<<16)
__device__ unsigned g_cx2[NPAIRS];
__device__ float2   g_tabA[2*NN];    // [bp][n] = {a[2bp][n], a[2bp+1][n]}
__device__ float2   g_tabB[2*NN];
__device__ float    g_piT[MM*MM];    // piT[k*64+j] = pi[j][k]
__device__ float    g_pi1[MM];
__device__ float    g_pi2[MM];
__device__ int      g_is64;

// ---------------- setup: softmax | dtype detect | a-table --------------------
__global__ void k_setup(const float* __restrict__ a0,
                        const float* __restrict__ Wm,
                        const unsigned* __restrict__ x1u) {
    int tid = threadIdx.x;
    if (blockIdx.x == 0) {
        // softmax over whole 64x64 W, write piT / pi1 / pi2
        __shared__ float sp[MM*MM];
        __shared__ float rbuf[256];
        float lm = -1e30f;
        for (int i = tid; i < MM*MM; i += 256) { float v = Wm[i]; sp[i] = v; lm = fmaxf(lm, v); }
        rbuf[tid] = lm; __syncthreads();
        for (int s = 128; s > 0; s >>= 1) { if (tid < s) rbuf[tid] = fmaxf(rbuf[tid], rbuf[tid+s]); __syncthreads(); }
        float m = rbuf[0]; __syncthreads();
        float ls = 0.f;
        for (int i = tid; i < MM*MM; i += 256) { float e = expf(sp[i] - m); sp[i] = e; ls += e; }
        rbuf[tid] = ls; __syncthreads();
        for (int s = 128; s > 0; s >>= 1) { if (tid < s) rbuf[tid] += rbuf[tid+s]; __syncthreads(); }
        float inv = 1.f / rbuf[0]; __syncthreads();
        for (int i = tid; i < MM*MM; i += 256) sp[i] *= inv;
        __syncthreads();
        for (int i = tid; i < MM*MM; i += 256) {
            int j = i >> 6, k = i & 63;
            g_piT[k*MM + j] = sp[i];
        }
        if (tid < MM) {
            float s = 0.f;
            for (int k = 0; k < MM; k++) s += sp[tid*MM + k];
            g_pi1[tid] = s;
        } else if (tid < 2*MM) {
            int k = tid - MM;
            float s = 0.f;
            for (int j = 0; j < MM; j++) s += sp[j*MM + k];
            g_pi2[k] = s;
        }
    } else if (blockIdx.x == 1) {
        // int64 vs int32 detection: int64 high words are all zero
        __shared__ int s_nz;
        if (tid == 0) s_nz = 0;
        __syncthreads();
        int nz = 0;
        for (int t = tid; t < 2048; t += 256)
            nz |= (x1u[2*t + 1] != 0u);
        if (nz) atomicOr(&s_nz, 1);
        __syncthreads();
        if (tid == 0) g_is64 = s_nz ? 0 : 1;
    } else {
        int i = (blockIdx.x - 2) * 256 + tid;
        if (i < NN) {
            g_tabA[i]      = make_float2(a0[i],        a0[NN + i]);
            g_tabA[NN + i] = make_float2(a0[2*NN + i], a0[3*NN + i]);
        }
    }
}

// ---------------- gather-max helper ------------------------------------------
__device__ __forceinline__ void gath_acc(unsigned v, const float2* __restrict__ tab, float2& f) {
    float2 A  = tab[v & 0xFFFFu];
    float2 Bv = tab[v >> 16];
    f.x = fmaxf(f.x, A.x * Bv.x);
    f.y = fmaxf(f.y, A.y * Bv.y);
}

// ---------------- main iteration kernel --------------------------------------
__global__ void __launch_bounds__(NT, 1) k_main(int iter,
                                                const void* __restrict__ x1,
                                                const void* __restrict__ x2,
                                                float* __restrict__ out) {
    extern __shared__ char smem[];
    float2* tab  = (float2*)smem;                    // [NN]
    float2* F1s  = (float2*)(smem + OFF_F1);         // [64][33]
    float2* F2T  = (float2*)(smem + OFF_F2T);        // [32][66]  (n-major, k inner)
    float*  piTs = (float*)(smem + OFF_PIT);         // [64][64]  piT[k][j]
    float*  pi1s = (float*)(smem + OFF_P12);
    float*  pi2s = pi1s + MM;
    float2* red  = (float2*)(smem + OFF_RED);        // [32][2]

    const int bp  = blockIdx.y;
    const float2* __restrict__ src = iter ? g_tabB : g_tabA;
    float2*       __restrict__ dst = iter ? g_tabA : g_tabB;
    const int tid = threadIdx.x;
    const int is64 = g_is64;

    for (int i = tid; i < NN; i += NT) tab[i] = src[bp*NN + i];
    for (int i = tid; i < MM*MM; i += NT) piTs[i] = g_piT[i];
    if (tid < MM) { pi1s[tid] = g_pi1[tid]; pi2s[tid] = g_pi2[tid]; }
    __syncthreads();

    const int warp = tid >> 5, lane = tid & 31;
    const int jj = tid & 63, grp = tid >> 6;         // grp 0..7
    const int half = (tid >> 5) & 1;

    for (int chunk = blockIdx.x; chunk < NCHUNK; chunk += GX) {
        const int n0 = chunk * NPB;

        // ======== phase 1: gather-max -> F1[j][n], F2T[n][k] ========
        #pragma unroll
        for (int p = 0; p < 4; p++) {
            const int j = p*16 + warp;
            const int n = n0 + lane;
            const size_t pb = ((size_t)j * NN + n) * WL;
            unsigned pk1[8], pk2[8];
            if (iter == 0) {
                if (is64) {
                    const uint4* c1 = (const uint4*)x1 + pb;
                    const uint4* c2 = (const uint4*)x2 + pb;
                    #pragma unroll
                    for (int w = 0; w < 8; w++) { uint4 v = __ldg(c1 + w); pk1[w] = v.x | (v.z << 16); }
                    #pragma unroll
                    for (int w = 0; w < 8; w++) { uint4 v = __ldg(c2 + w); pk2[w] = v.x | (v.z << 16); }
                } else {
                    const uint4* c1 = (const uint4*)x1 + (pb >> 1);
                    const uint4* c2 = (const uint4*)x2 + (pb >> 1);
                    #pragma unroll
                    for (int w = 0; w < 4; w++) {
                        uint4 v = __ldg(c1 + w);
                        pk1[2*w] = v.x | (v.y << 16); pk1[2*w+1] = v.z | (v.w << 16);
                    }
                    #pragma unroll
                    for (int w = 0; w < 4; w++) {
                        uint4 v = __ldg(c2 + w);
                        pk2[2*w] = v.x | (v.y << 16); pk2[2*w+1] = v.z | (v.w << 16);
                    }
                }
                if (bp == 0) {   // stash packed indices for iter 2
                    uint4* s1 = (uint4*)(g_cx1 + pb);
                    uint4* s2 = (uint4*)(g_cx2 + pb);
                    s1[0] = make_uint4(pk1[0], pk1[1], pk1[2], pk1[3]);
                    s1[1] = make_uint4(pk1[4], pk1[5], pk1[6], pk1[7]);
                    s2[0] = make_uint4(pk2[0], pk2[1], pk2[2], pk2[3]);
                    s2[1] = make_uint4(pk2[4], pk2[5], pk2[6], pk2[7]);
                }
            } else {
                const uint4* c1 = (const uint4*)(g_cx1 + pb);
                const uint4* c2 = (const uint4*)(g_cx2 + pb);
                uint4 q0 = __ldg(c1), q1 = __ldg(c1 + 1);
                uint4 r0 = __ldg(c2), r1 = __ldg(c2 + 1);
                pk1[0]=q0.x; pk1[1]=q0.y; pk1[2]=q0.z; pk1[3]=q0.w;
                pk1[4]=q1.x; pk1[5]=q1.y; pk1[6]=q1.z; pk1[7]=q1.w;
                pk2[0]=r0.x; pk2[1]=r0.y; pk2[2]=r0.z; pk2[3]=r0.w;
                pk2[4]=r1.x; pk2[5]=r1.y; pk2[6]=r1.z; pk2[7]=r1.w;
            }
            float2 f1 = make_float2(0.f, 0.f);   // products >= 0
            float2 f2 = make_float2(0.f, 0.f);
            #pragma unroll
            for (int w = 0; w < 8; w++) gath_acc(pk1[w], tab, f1);
            #pragma unroll
            for (int w = 0; w < 8; w++) gath_acc(pk2[w], tab, f2);
            F1s[j*33 + lane] = f1;
            F2T[lane*66 + j] = f2;
        }
        __syncthreads();

        // ======== phase 2: derived = pi1.F1 + pi2.F2 - F1.(pi@F2) ========
        {
            float2 mv[4];
            #pragma unroll
            for (int r = 0; r < 4; r++) mv[r] = make_float2(0.f, 0.f);
            #pragma unroll 8
            for (int k = 0; k < MM; k += 2) {
                float pw0 = piTs[k*MM + jj];
                float pw1 = piTs[(k+1)*MM + jj];
                #pragma unroll
                for (int r = 0; r < 4; r++) {
                    const int nl = r*8 + grp;
                    float4 fk = *(const float4*)&F2T[nl*66 + k];  // k and k+1 (16B aligned: 66 even)
                    mv[r].x = fmaf(pw0, fk.x, mv[r].x);
                    mv[r].y = fmaf(pw0, fk.y, mv[r].y);
                    mv[r].x = fmaf(pw1, fk.z, mv[r].x);
                    mv[r].y = fmaf(pw1, fk.w, mv[r].y);
                }
            }
            const float p1 = pi1s[jj], p2 = pi2s[jj];
            #pragma unroll
            for (int r = 0; r < 4; r++) {
                const int nl = r*8 + grp;
                float2 f1 = F1s[jj*33 + nl];
                float2 f2 = F2T[nl*66 + jj];
                float2 c;
                c.x = p1*f1.x + p2*f2.x - f1.x*mv[r].x;
                c.y = p1*f1.y + p2*f2.y - f1.y*mv[r].y;
                #pragma unroll
                for (int off = 16; off > 0; off >>= 1) {
                    c.x += __shfl_xor_sync(0xFFFFFFFFu, c.x, off);
                    c.y += __shfl_xor_sync(0xFFFFFFFFu, c.y, off);
                }
                if (lane == 0) red[nl*2 + half] = c;
            }
        }
        __syncthreads();

        // ======== fuse: a' = 1 - (1-a)(1-derived), write dst (+out) ========
        if (tid < NPB) {
            const int nl = tid;
            const int n  = n0 + nl;
            float2 d0 = red[nl*2], d1 = red[nl*2 + 1];
            float dx = d0.x + d1.x, dy = d0.y + d1.y;
            float2 ao = tab[n];
            float2 an;
            an.x = 1.f - (1.f - ao.x) * (1.f - dx);
            an.y = 1.f - (1.f - ao.y) * (1.f - dy);
            dst[bp*NN + n] = an;
            if (iter) {
                out[(2*bp)*NN + n]     = an.x;
                out[(2*bp + 1)*NN + n] = an.y;
            }
        }
        __syncthreads();
    }
}

// ---------------- launcher ----------------------------------------------------
extern "C" void kernel_launch(void* const* d_in, const int* in_sizes, int n_in,
                              void* d_out, int out_size) {
    const float* a0 = (const float*)d_in[0];
    const float* Wm = (const float*)d_in[1];
    const void*  x1 = d_in[2];
    const void*  x2 = d_in[3];
    float* out = (float*)d_out;

    cudaFuncSetAttribute(k_main, cudaFuncAttributeMaxDynamicSharedMemorySize, SMEM_TOTAL);

    k_setup<<<2 + (NN + 255)/256, 256>>>(a0, Wm, (const unsigned*)x1);

    dim3 g(GX, 2);
    k_main<<<g, NT, SMEM_TOTAL>>>(0, x1, x2, out);   // iter 1: raw X -> packed + tabB
    k_main<<<g, NT, SMEM_TOTAL>>>(1, x1, x2, out);   // iter 2: packed -> tabA + d_out
}